// round 7
// baseline (speedup 1.0000x reference)
#include <cuda_runtime.h>
#include <cuda_bf16.h>
#include <math.h>
#include <stdint.h>

#define T_LEN 8192
#define HALF  4096
#define CH    128
#define BATCH 16
#define NSIG  (BATCH * CH)
#define KSPLIT 16
#define KC    32                          // K per chunk
#define NC    (T_LEN / KSPLIT / KC)       // 16 chunks per CTA
#define ROWSTRIDE 40                      // bf16 elems per smem row (32 + 8 pad)
#define MATBYTES (128 * ROWSTRIDE * 2)    // 10240
#define BUFBYTES (4 * MATBYTES)           // 40960

// Scratch (alloc-free rule: __device__ globals)
__device__ __nv_bfloat16 g_ph[(size_t)BATCH * 256 * T_LEN];   // hi parts: 64 MB
__device__ __nv_bfloat16 g_pl[(size_t)BATCH * 256 * T_LEN];   // lo parts: 64 MB
__device__ float g_gram[(size_t)KSPLIT * BATCH * 3 * CH * CH];// Gram tiles: 48 MB

// ===========================================================================
// PTX helpers (sm_103 family-portable: ldmatrix / mma.sync / cp.async)
// ===========================================================================
__device__ __forceinline__ uint32_t smem_u32(const void* p) {
    uint32_t a;
    asm("{ .reg .u64 t; cvta.to.shared.u64 t, %1; cvt.u32.u64 %0, t; }"
        : "=r"(a) : "l"(p));
    return a;
}
__device__ __forceinline__ void ldsm4(uint32_t* d, uint32_t addr) {
    asm volatile("ldmatrix.sync.aligned.m8n8.x4.shared.b16 {%0,%1,%2,%3}, [%4];"
                 : "=r"(d[0]), "=r"(d[1]), "=r"(d[2]), "=r"(d[3]) : "r"(addr));
}
__device__ __forceinline__ void ldsm2(uint32_t* d, uint32_t addr) {
    asm volatile("ldmatrix.sync.aligned.m8n8.x2.shared.b16 {%0,%1}, [%2];"
                 : "=r"(d[0]), "=r"(d[1]) : "r"(addr));
}
__device__ __forceinline__ void mma_bf16(float* d, const uint32_t* a, const uint32_t* b) {
    asm volatile(
        "mma.sync.aligned.m16n8k16.row.col.f32.bf16.bf16.f32 "
        "{%0,%1,%2,%3}, {%4,%5,%6,%7}, {%8,%9}, {%0,%1,%2,%3};"
        : "+f"(d[0]), "+f"(d[1]), "+f"(d[2]), "+f"(d[3])
        : "r"(a[0]), "r"(a[1]), "r"(a[2]), "r"(a[3]), "r"(b[0]), "r"(b[1]));
}
__device__ __forceinline__ void cp16(uint32_t smem, const void* g) {
    asm volatile("cp.async.cg.shared.global [%0], [%1], 16;"
                 :: "r"(smem), "l"(g) : "memory");
}
#define CP_COMMIT() asm volatile("cp.async.commit_group;" ::: "memory")
#define CP_WAIT1()  asm volatile("cp.async.wait_group 1;" ::: "memory")
#define CP_WAIT0()  asm volatile("cp.async.wait_group 0;" ::: "memory")

// ===========================================================================
// Kernel 1: register-resident FFT -> analytic signal -> unit phase vectors.
// Distinct-twiddle hoisting (15 loads per 4-stage group instead of 32).
// Epilogue stages packed bf16x2 words in smem; global stores are STG.128.
// ===========================================================================
__device__ __forceinline__ int swz(int i) { return i ^ ((i >> 5) & 31); }

template<int P, int FWD, int LBLO, int LBHI>
__device__ __forceinline__ void stages(float2 v[16], int base, const float2* __restrict__ tw) {
#pragma unroll
    for (int t = 0; t <= LBHI - LBLO; t++) {
        const int lb = FWD ? (LBHI - t) : (LBLO + t);
        const int s  = P + lb;
        const int bm = base & ((1 << s) - 1);
        const int nw = 1 << lb;
        float2 wreg[4];
        if (lb < 3) {
#pragma unroll
            for (int q = 0; q < 4; q++)
                if (q < nw) wreg[q] = tw[(bm + (q << P)) << (12 - s)];
        }
#pragma unroll
        for (int g = 0; g < (16 >> (lb + 1)); g++) {
#pragma unroll
            for (int q = 0; q < nw; q++) {
                const int r0 = (g << (lb + 1)) + q;
                const int r1 = r0 + nw;
                const float2 w = (lb < 3) ? wreg[q]
                                          : tw[(bm + (q << P)) << (12 - s)];
                float2 a = v[r0], b = v[r1];
                if (FWD) {
                    v[r0] = make_float2(a.x + b.x, a.y + b.y);
                    float2 d = make_float2(a.x - b.x, a.y - b.y);
                    v[r1] = make_float2(d.x * w.x - d.y * w.y,
                                        d.x * w.y + d.y * w.x);
                } else {
                    float2 tt = make_float2(b.x * w.x + b.y * w.y,
                                            b.y * w.x - b.x * w.y);
                    v[r0] = make_float2(a.x + tt.x, a.y + tt.y);
                    v[r1] = make_float2(a.x - tt.x, a.y - tt.y);
                }
            }
        }
    }
}

extern __shared__ float2 smm[];   // fft: [0..8191]=exchange, [8192..12287]=twiddles

__global__ void __launch_bounds__(512) fft_kernel(const float* __restrict__ x) {
    float2* sm = smm;
    float2* tw = smm + T_LEN;
    const int tid = threadIdx.x;
    const long long gbase = (long long)blockIdx.x * T_LEN;

    for (int t = tid; t < HALF; t += 512) {
        float s, c;
        sincosf(-6.283185307179586e0f * (float)t / (float)T_LEN, &s, &c);
        tw[t] = make_float2(c, s);
    }

    const int baseA = tid;
    const int baseB = ((tid >> 5) << 9) + (tid & 31);
    const int baseC = ((tid >> 1) << 5) + (tid & 1);
    const int baseD = tid << 4;
    const int baseE = ((tid >> 4) << 8) + (tid & 15);
    const int baseF = ((tid >> 8) << 12) + (tid & 255);

    float2 v[16];
#pragma unroll
    for (int r = 0; r < 16; r++)
        v[r] = make_float2(x[gbase + tid + r * 512], 0.0f);
    __syncthreads();

    stages<9, 1, 0, 3>(v, baseA, tw);
#pragma unroll
    for (int r = 0; r < 16; r++) sm[swz(baseA + (r << 9))] = v[r];
    __syncthreads();
#pragma unroll
    for (int r = 0; r < 16; r++) v[r] = sm[swz(baseB + (r << 5))];
    __syncthreads();

    stages<5, 1, 0, 3>(v, baseB, tw);
#pragma unroll
    for (int r = 0; r < 16; r++) sm[swz(baseB + (r << 5))] = v[r];
    __syncthreads();
#pragma unroll
    for (int r = 0; r < 16; r++) v[r] = sm[swz(baseC + (r << 1))];
    __syncthreads();

    stages<1, 1, 0, 3>(v, baseC, tw);
#pragma unroll
    for (int r = 0; r < 16; r++) sm[swz(baseC + (r << 1))] = v[r];
    __syncthreads();
#pragma unroll
    for (int r = 0; r < 16; r++) v[r] = sm[swz(baseD + r)];
    __syncthreads();

#pragma unroll
    for (int r = 0; r < 16; r += 2) {
        float2 s0 = make_float2(v[r].x + v[r + 1].x, v[r].y + v[r + 1].y);
        v[r] = s0; v[r + 1] = s0;
    }

    stages<0, 0, 1, 3>(v, baseD, tw);
#pragma unroll
    for (int r = 0; r < 16; r++) sm[swz(baseD + r)] = v[r];
    __syncthreads();
#pragma unroll
    for (int r = 0; r < 16; r++) v[r] = sm[swz(baseE + (r << 4))];
    __syncthreads();

    stages<4, 0, 0, 3>(v, baseE, tw);
#pragma unroll
    for (int r = 0; r < 16; r++) sm[swz(baseE + (r << 4))] = v[r];
    __syncthreads();
#pragma unroll
    for (int r = 0; r < 16; r++) v[r] = sm[swz(baseF + (r << 8))];
    __syncthreads();

    stages<8, 0, 0, 3>(v, baseF, tw);
#pragma unroll
    for (int r = 0; r < 16; r++) sm[swz(baseF + (r << 8))] = v[r];
    __syncthreads();
#pragma unroll
    for (int r = 0; r < 16; r++) v[r] = sm[swz(baseA + (r << 9))];
    __syncthreads();

    stages<9, 0, 3, 3>(v, baseA, tw);

    // ---- epilogue: normalize, bf16 hi/lo split, packed smem staging ----
    // smem reuse (64 KB): sbA[t] = (chh | shh<<16), sbB[t] = (cll | sll<<16)
    uint32_t* sbA = (uint32_t*)sm;
    uint32_t* sbB = sbA + T_LEN;
#pragma unroll
    for (int r = 0; r < 16; r++) {
        const int t = tid + r * 512;
        float2 u = v[r];
        float m2 = u.x * u.x + u.y * u.y;
        float cx, sx;
        if (m2 > 0.0f) {
            float inv = rsqrtf(m2);
            cx = u.x * inv; sx = u.y * inv;
        } else {
            cx = 1.0f; sx = 0.0f;
        }
        __nv_bfloat16 chh = __float2bfloat16(cx);
        __nv_bfloat16 cll = __float2bfloat16(cx - __bfloat162float(chh));
        __nv_bfloat16 shh = __float2bfloat16(sx);
        __nv_bfloat16 sll = __float2bfloat16(sx - __bfloat162float(shh));
        sbA[t] = (uint32_t)__bfloat16_as_ushort(chh)
               | ((uint32_t)__bfloat16_as_ushort(shh) << 16);
        sbB[t] = (uint32_t)__bfloat16_as_ushort(cll)
               | ((uint32_t)__bfloat16_as_ushort(sll) << 16);
    }
    __syncthreads();

    const int bb = blockIdx.x >> 7;
    const int cc = blockIdx.x & 127;
    const size_t rowc = ((size_t)bb * 256 + cc) * T_LEN;
    const size_t rows = rowc + (size_t)128 * T_LEN;

    // Each thread covers t in [16*tid, 16*tid+16): unzip pairs -> STG.128
    const uint4* A4 = (const uint4*)sbA;
    const uint4* B4 = (const uint4*)sbB;
    uint4 a0 = A4[4 * tid], a1 = A4[4 * tid + 1];
    uint4 a2 = A4[4 * tid + 2], a3 = A4[4 * tid + 3];
    uint4 b0 = B4[4 * tid], b1 = B4[4 * tid + 1];
    uint4 b2 = B4[4 * tid + 2], b3 = B4[4 * tid + 3];

    uint4 c0 = make_uint4(__byte_perm(a0.x, a0.y, 0x5410), __byte_perm(a0.z, a0.w, 0x5410),
                          __byte_perm(a1.x, a1.y, 0x5410), __byte_perm(a1.z, a1.w, 0x5410));
    uint4 c1 = make_uint4(__byte_perm(a2.x, a2.y, 0x5410), __byte_perm(a2.z, a2.w, 0x5410),
                          __byte_perm(a3.x, a3.y, 0x5410), __byte_perm(a3.z, a3.w, 0x5410));
    uint4 s0 = make_uint4(__byte_perm(a0.x, a0.y, 0x7632), __byte_perm(a0.z, a0.w, 0x7632),
                          __byte_perm(a1.x, a1.y, 0x7632), __byte_perm(a1.z, a1.w, 0x7632));
    uint4 s1 = make_uint4(__byte_perm(a2.x, a2.y, 0x7632), __byte_perm(a2.z, a2.w, 0x7632),
                          __byte_perm(a3.x, a3.y, 0x7632), __byte_perm(a3.z, a3.w, 0x7632));
    uint4 e0 = make_uint4(__byte_perm(b0.x, b0.y, 0x5410), __byte_perm(b0.z, b0.w, 0x5410),
                          __byte_perm(b1.x, b1.y, 0x5410), __byte_perm(b1.z, b1.w, 0x5410));
    uint4 e1 = make_uint4(__byte_perm(b2.x, b2.y, 0x5410), __byte_perm(b2.z, b2.w, 0x5410),
                          __byte_perm(b3.x, b3.y, 0x5410), __byte_perm(b3.z, b3.w, 0x5410));
    uint4 f0 = make_uint4(__byte_perm(b0.x, b0.y, 0x7632), __byte_perm(b0.z, b0.w, 0x7632),
                          __byte_perm(b1.x, b1.y, 0x7632), __byte_perm(b1.z, b1.w, 0x7632));
    uint4 f1 = make_uint4(__byte_perm(b2.x, b2.y, 0x7632), __byte_perm(b2.z, b2.w, 0x7632),
                          __byte_perm(b3.x, b3.y, 0x7632), __byte_perm(b3.z, b3.w, 0x7632));

    ((uint4*)(g_ph + rowc))[2 * tid]     = c0;
    ((uint4*)(g_ph + rowc))[2 * tid + 1] = c1;
    ((uint4*)(g_ph + rows))[2 * tid]     = s0;
    ((uint4*)(g_ph + rows))[2 * tid + 1] = s1;
    ((uint4*)(g_pl + rowc))[2 * tid]     = e0;
    ((uint4*)(g_pl + rowc))[2 * tid + 1] = e1;
    ((uint4*)(g_pl + rows))[2 * tid]     = f0;
    ((uint4*)(g_pl + rows))[2 * tid + 1] = f1;
}

// ===========================================================================
// Kernel 2: bf16 hi/lo-split Gram via mma.sync.m16n8k16 (unchanged from R6).
// ===========================================================================
extern __shared__ __align__(128) char gsm[];   // 2 * BUFBYTES = 80 KB

__global__ void __launch_bounds__(256, 2) gram_mma() {
    const int tid  = threadIdx.x;
    const int wid  = tid >> 5;
    const int lane = tid & 31;
    const int ks   = blockIdx.x;
    const int tile = blockIdx.y;
    const int b    = blockIdx.z;
    const int ms   = (tile >= 1) ? 1 : 0;
    const int ns   = (tile == 1) ? 1 : 0;
    const bool diag = (ms == ns);

    const uint32_t sb = smem_u32(gsm);
    const size_t k0 = (size_t)ks * (T_LEN / KSPLIT);

    const int sub  = tid & 3;
    const int vrw  = tid >> 2;
    const int npass = diag ? 4 : 8;

    int prow[8]; const __nv_bfloat16* psrc[8]; uint32_t pdst[8];
#pragma unroll
    for (int p = 0; p < 8; p++) {
        const int vr = vrw + p * 64;
        const int q  = vr >> 7;              // 0=Ahi 1=Alo 2=Bhi 3=Blo
        const int r  = vr & 127;
        psrc[p] = (q & 1) ? g_pl : g_ph;
        prow[p] = (b * 256 + ((q < 2) ? ms : ns) * 128 + r);
        pdst[p] = (uint32_t)(q * MATBYTES + r * (ROWSTRIDE * 2) + sub * 16);
    }

    auto load_chunk = [&](int c) {
        const uint32_t bufb = sb + (uint32_t)((c & 1) * BUFBYTES);
        const size_t kofs = k0 + (size_t)c * KC + sub * 8;
#pragma unroll
        for (int p = 0; p < 8; p++) {
            if (p >= npass) break;
            cp16(bufb + pdst[p], psrc[p] + (size_t)prow[p] * T_LEN + kofs);
        }
        CP_COMMIT();
    };

    const int mrow0 = (wid >> 2) * 64;
    const int ncol0 = (wid & 3) * 32;

    float acc[4][4][4];
#pragma unroll
    for (int mt = 0; mt < 4; mt++)
#pragma unroll
        for (int nt = 0; nt < 4; nt++)
#pragma unroll
            for (int e = 0; e < 4; e++) acc[mt][nt][e] = 0.0f;

    const uint32_t bOfsHi = diag ? 0u : (uint32_t)(2 * MATBYTES);
    const uint32_t bOfsLo = diag ? (uint32_t)MATBYTES : (uint32_t)(3 * MATBYTES);

    load_chunk(0);
    for (int c = 0; c < NC; c++) {
        if (c + 1 < NC) { load_chunk(c + 1); CP_WAIT1(); }
        else           { CP_WAIT0(); }
        __syncthreads();

        const uint32_t bufb = sb + (uint32_t)((c & 1) * BUFBYTES);
#pragma unroll
        for (int kstep = 0; kstep < KC / 16; kstep++) {
            uint32_t bh[4][2], bl[4][2];
            const int brow  = ncol0 + (lane & 7);
            const int bcolb = ((((lane >> 3) & 1) << 3) + kstep * 16) * 2;
#pragma unroll
            for (int nt = 0; nt < 4; nt++) {
                const uint32_t bo = (uint32_t)((brow + nt * 8) * (ROWSTRIDE * 2) + bcolb);
                ldsm2(bh[nt], bufb + bOfsHi + bo);
                ldsm2(bl[nt], bufb + bOfsLo + bo);
            }
            const int arow  = mrow0 + (lane & 15);
            const int acolb = (((lane >> 4) << 3) + kstep * 16) * 2;
#pragma unroll
            for (int mt = 0; mt < 4; mt++) {
                uint32_t ah[4], al[4];
                const uint32_t ao = (uint32_t)((arow + mt * 16) * (ROWSTRIDE * 2) + acolb);
                ldsm4(ah, bufb + ao);
                ldsm4(al, bufb + MATBYTES + ao);
#pragma unroll
                for (int nt = 0; nt < 4; nt++) {
                    mma_bf16(acc[mt][nt], ah, bh[nt]);
                    mma_bf16(acc[mt][nt], ah, bl[nt]);
                    mma_bf16(acc[mt][nt], al, bh[nt]);
                }
            }
        }
        __syncthreads();
    }

    float* __restrict__ G =
        g_gram + ((size_t)((ks * BATCH + b) * 3 + tile)) * (CH * CH);
    const int r0 = lane >> 2;
    const int c0 = (lane & 3) * 2;
#pragma unroll
    for (int mt = 0; mt < 4; mt++) {
        const int row = mrow0 + mt * 16 + r0;
#pragma unroll
        for (int nt = 0; nt < 4; nt++) {
            const int col = ncol0 + nt * 8 + c0;
            *(float2*)(G + row * CH + col) =
                make_float2(acc[mt][nt][0], acc[mt][nt][1]);
            *(float2*)(G + (row + 8) * CH + col) =
                make_float2(acc[mt][nt][2], acc[mt][nt][3]);
        }
    }
}

// ===========================================================================
// Kernel 3: combine K-splits; Re = CC+SS, Im = SC[i,j]-SC[j,i]; PLV=|.|/T.
// ===========================================================================
__global__ void finalize_kernel(float* __restrict__ out) {
    const int idx = blockIdx.x * blockDim.x + threadIdx.x;
    if (idx >= BATCH * CH * CH) return;
    const int b  = idx >> 14;
    const int ij = idx & 16383;
    const int i  = ij >> 7;
    const int j  = ij & 127;
    float re = 0.0f, im = 0.0f;
#pragma unroll
    for (int ks = 0; ks < KSPLIT; ks++) {
        const float* __restrict__ base =
            g_gram + ((size_t)((ks * BATCH + b) * 3)) * (CH * CH);
        re += base[ij] + base[CH * CH + ij];                       // CC + SS
        im += base[2 * CH * CH + i * CH + j]
            - base[2 * CH * CH + j * CH + i];                      // SC - SC^T
    }
    out[idx] = sqrtf(re * re + im * im) * (1.0f / (float)T_LEN);
}

// ===========================================================================
extern "C" void kernel_launch(void* const* d_in, const int* in_sizes, int n_in,
                              void* d_out, int out_size) {
    const float* x = (const float*)d_in[0];
    float* out = (float*)d_out;

    const int fft_smem = (T_LEN + HALF) * (int)sizeof(float2);  // 96 KB
    cudaFuncSetAttribute(fft_kernel, cudaFuncAttributeMaxDynamicSharedMemorySize,
                         fft_smem);
    cudaFuncSetAttribute(gram_mma, cudaFuncAttributeMaxDynamicSharedMemorySize,
                         2 * BUFBYTES);

    fft_kernel<<<NSIG, 512, fft_smem>>>(x);
    gram_mma<<<dim3(KSPLIT, 3, BATCH), 256, 2 * BUFBYTES>>>();
    finalize_kernel<<<(BATCH * CH * CH + 255) / 256, 256>>>(out);
}

// round 8
// speedup vs baseline: 1.1391x; 1.1391x over previous
#include <cuda_runtime.h>
#include <cuda_bf16.h>
#include <math.h>
#include <stdint.h>

#define T_LEN 8192
#define HALF  4096
#define CH    128
#define BATCH 16
#define NSIG  (BATCH * CH)
#define KSPLIT 16
#define KC    32                          // K per chunk
#define NC    (T_LEN / KSPLIT / KC)       // 16 chunks per CTA
#define ROWSTRIDE 40                      // bf16 elems per smem row (32 + 8 pad)
#define MATBYTES (128 * ROWSTRIDE * 2)    // 10240
#define BUFBYTES (4 * MATBYTES)           // 40960

// Scratch (alloc-free rule: __device__ globals)
__device__ __nv_bfloat16 g_ph[(size_t)BATCH * 256 * T_LEN];   // hi parts: 64 MB
__device__ __nv_bfloat16 g_pl[(size_t)BATCH * 256 * T_LEN];   // lo parts: 64 MB
__device__ float g_gram[(size_t)KSPLIT * BATCH * 3 * CH * CH];// Gram tiles: 48 MB

// ===========================================================================
// PTX helpers (sm_103 family-portable: ldmatrix / mma.sync / cp.async)
// ===========================================================================
__device__ __forceinline__ uint32_t smem_u32(const void* p) {
    uint32_t a;
    asm("{ .reg .u64 t; cvta.to.shared.u64 t, %1; cvt.u32.u64 %0, t; }"
        : "=r"(a) : "l"(p));
    return a;
}
__device__ __forceinline__ void ldsm4(uint32_t* d, uint32_t addr) {
    asm volatile("ldmatrix.sync.aligned.m8n8.x4.shared.b16 {%0,%1,%2,%3}, [%4];"
                 : "=r"(d[0]), "=r"(d[1]), "=r"(d[2]), "=r"(d[3]) : "r"(addr));
}
__device__ __forceinline__ void ldsm2(uint32_t* d, uint32_t addr) {
    asm volatile("ldmatrix.sync.aligned.m8n8.x2.shared.b16 {%0,%1}, [%2];"
                 : "=r"(d[0]), "=r"(d[1]) : "r"(addr));
}
__device__ __forceinline__ void mma_bf16(float* d, const uint32_t* a, const uint32_t* b) {
    asm volatile(
        "mma.sync.aligned.m16n8k16.row.col.f32.bf16.bf16.f32 "
        "{%0,%1,%2,%3}, {%4,%5,%6,%7}, {%8,%9}, {%0,%1,%2,%3};"
        : "+f"(d[0]), "+f"(d[1]), "+f"(d[2]), "+f"(d[3])
        : "r"(a[0]), "r"(a[1]), "r"(a[2]), "r"(a[3]), "r"(b[0]), "r"(b[1]));
}
__device__ __forceinline__ void cp16(uint32_t smem, const void* g) {
    asm volatile("cp.async.cg.shared.global [%0], [%1], 16;"
                 :: "r"(smem), "l"(g) : "memory");
}
#define CP_COMMIT() asm volatile("cp.async.commit_group;" ::: "memory")
#define CP_WAIT1()  asm volatile("cp.async.wait_group 1;" ::: "memory")
#define CP_WAIT0()  asm volatile("cp.async.wait_group 0;" ::: "memory")

// ===========================================================================
// Kernel 1: register-resident FFT, 8 elements/thread x 1024 threads.
// R6-proven butterfly structure (fully unrolled rr-loop), 3 stages per group,
// 8 swizzled exchanges. Fused fwd-stage0 + mask + inv-stage0.
// ===========================================================================
__device__ __forceinline__ int swz(int i) { return i ^ ((i >> 5) & 31); }

template<int P, int FWD, int LBLO, int LBHI>
__device__ __forceinline__ void stages(float2 v[8], int base, const float2* __restrict__ tw) {
#pragma unroll
    for (int t = 0; t <= LBHI - LBLO; t++) {
        const int lb = FWD ? (LBHI - t) : (LBLO + t);
        const int s  = P + lb;
        const int bm = base & ((1 << s) - 1);
#pragma unroll
        for (int rr = 0; rr < 8; rr++) {
            if ((rr >> lb) & 1) continue;
            const int r1 = rr | (1 << lb);
            const int j  = bm + ((rr & ((1 << lb) - 1)) << P);
            const float2 w = tw[j << (12 - s)];
            float2 a = v[rr], b = v[r1];
            if (FWD) {
                v[rr] = make_float2(a.x + b.x, a.y + b.y);
                float2 d = make_float2(a.x - b.x, a.y - b.y);
                v[r1] = make_float2(d.x * w.x - d.y * w.y, d.x * w.y + d.y * w.x);
            } else {
                float2 tt = make_float2(b.x * w.x + b.y * w.y, b.y * w.x - b.x * w.y);
                v[rr] = make_float2(a.x + tt.x, a.y + tt.y);
                v[r1] = make_float2(a.x - tt.x, a.y - tt.y);
            }
        }
    }
}

extern __shared__ float2 smm[];   // fft: [0..8191]=exchange, [8192..12287]=twiddles

#define XCHG(baseExpr, SH) \
    do { \
        const int _b = (baseExpr); \
        _Pragma("unroll") \
        for (int r = 0; r < 8; r++) sm[swz(_b + (r << (SH)))] = v[r]; \
    } while (0)
#define XLD(baseExpr, SH) \
    do { \
        const int _b = (baseExpr); \
        _Pragma("unroll") \
        for (int r = 0; r < 8; r++) v[r] = sm[swz(_b + (r << (SH)))]; \
    } while (0)

__global__ void __launch_bounds__(1024) fft_kernel(const float* __restrict__ x) {
    float2* sm = smm;
    float2* tw = smm + T_LEN;
    const int tid = threadIdx.x;
    const long long gbase = (long long)blockIdx.x * T_LEN;

    for (int t = tid; t < HALF; t += 1024) {
        float s, c;
        sincosf(-6.283185307179586e0f * (float)t / (float)T_LEN, &s, &c);
        tw[t] = make_float2(c, s);
    }

    // Layout bases: idx = base + r * 2^P
    const int baseA = tid;                                    // P=10
    const int baseB = ((tid >> 7) << 10) | (tid & 127);       // P=7
    const int baseC = ((tid >> 4) << 7)  | (tid & 15);        // P=4
    const int baseD = ((tid >> 1) << 4)  | (tid & 1);         // P=1
    const int baseE = tid << 3;                               // P=0
    const int baseF = ((tid >> 3) << 6)  | (tid & 7);         // P=3
    const int baseG = ((tid >> 6) << 9)  | (tid & 63);        // P=6
    const int baseH = ((tid >> 9) << 12) | (tid & 511);       // P=9

    float2 v[8];
#pragma unroll
    for (int r = 0; r < 8; r++)
        v[r] = make_float2(x[gbase + tid + r * 1024], 0.0f);
    __syncthreads();   // tw ready

    // ---- forward DIF: s = 12..1 ----
    stages<10, 1, 0, 2>(v, baseA, tw);      // 12,11,10
    XCHG(baseA, 10); __syncthreads(); XLD(baseB, 7); __syncthreads();
    stages<7, 1, 0, 2>(v, baseB, tw);       // 9,8,7
    XCHG(baseB, 7); __syncthreads(); XLD(baseC, 4); __syncthreads();
    stages<4, 1, 0, 2>(v, baseC, tw);       // 6,5,4
    XCHG(baseC, 4); __syncthreads(); XLD(baseD, 1); __syncthreads();
    stages<1, 1, 0, 2>(v, baseD, tw);       // 3,2,1
    XCHG(baseD, 1); __syncthreads(); XLD(baseE, 0); __syncthreads();

    // Fused: fwd stage 0 (w=1) + mask(odd bit-rev pos) + inv stage 0.
#pragma unroll
    for (int r = 0; r < 8; r += 2) {
        float2 s0 = make_float2(v[r].x + v[r + 1].x, v[r].y + v[r + 1].y);
        v[r] = s0; v[r + 1] = s0;
    }

    // ---- inverse DIT: s = 1..12 ----
    stages<0, 0, 1, 2>(v, baseE, tw);       // 1,2
    XCHG(baseE, 0); __syncthreads(); XLD(baseF, 3); __syncthreads();
    stages<3, 0, 0, 2>(v, baseF, tw);       // 3,4,5
    XCHG(baseF, 3); __syncthreads(); XLD(baseG, 6); __syncthreads();
    stages<6, 0, 0, 2>(v, baseG, tw);       // 6,7,8
    XCHG(baseG, 6); __syncthreads(); XLD(baseH, 9); __syncthreads();
    stages<9, 0, 0, 2>(v, baseH, tw);       // 9,10,11
    XCHG(baseH, 9); __syncthreads(); XLD(baseA, 10); __syncthreads();
    stages<10, 0, 2, 2>(v, baseA, tw);      // 12

    // ---- epilogue: normalize, bf16 hi/lo split, packed smem staging ----
    uint32_t* sbA = (uint32_t*)sm;          // (chh | shh<<16) per t
    uint32_t* sbB = sbA + T_LEN;            // (cll | sll<<16)
#pragma unroll
    for (int r = 0; r < 8; r++) {
        const int t = tid + r * 1024;
        float2 u = v[r];
        float m2 = u.x * u.x + u.y * u.y;
        float cx, sx;
        if (m2 > 0.0f) {
            float inv = rsqrtf(m2);
            cx = u.x * inv; sx = u.y * inv;
        } else {
            cx = 1.0f; sx = 0.0f;
        }
        __nv_bfloat16 chh = __float2bfloat16(cx);
        __nv_bfloat16 cll = __float2bfloat16(cx - __bfloat162float(chh));
        __nv_bfloat16 shh = __float2bfloat16(sx);
        __nv_bfloat16 sll = __float2bfloat16(sx - __bfloat162float(shh));
        sbA[t] = (uint32_t)__bfloat16_as_ushort(chh)
               | ((uint32_t)__bfloat16_as_ushort(shh) << 16);
        sbB[t] = (uint32_t)__bfloat16_as_ushort(cll)
               | ((uint32_t)__bfloat16_as_ushort(sll) << 16);
    }
    __syncthreads();

    const int bb = blockIdx.x >> 7;
    const int cc = blockIdx.x & 127;
    const size_t rowc = ((size_t)bb * 256 + cc) * T_LEN;
    const size_t rows = rowc + (size_t)128 * T_LEN;

    // Each thread covers t in [8*tid, 8*tid+8): unzip -> one STG.128 per array
    const uint4* A4 = (const uint4*)sbA;
    const uint4* B4 = (const uint4*)sbB;
    uint4 a0 = A4[2 * tid], a1 = A4[2 * tid + 1];
    uint4 b0 = B4[2 * tid], b1 = B4[2 * tid + 1];

    uint4 c0 = make_uint4(__byte_perm(a0.x, a0.y, 0x5410), __byte_perm(a0.z, a0.w, 0x5410),
                          __byte_perm(a1.x, a1.y, 0x5410), __byte_perm(a1.z, a1.w, 0x5410));
    uint4 s0 = make_uint4(__byte_perm(a0.x, a0.y, 0x7632), __byte_perm(a0.z, a0.w, 0x7632),
                          __byte_perm(a1.x, a1.y, 0x7632), __byte_perm(a1.z, a1.w, 0x7632));
    uint4 e0 = make_uint4(__byte_perm(b0.x, b0.y, 0x5410), __byte_perm(b0.z, b0.w, 0x5410),
                          __byte_perm(b1.x, b1.y, 0x5410), __byte_perm(b1.z, b1.w, 0x5410));
    uint4 f0 = make_uint4(__byte_perm(b0.x, b0.y, 0x7632), __byte_perm(b0.z, b0.w, 0x7632),
                          __byte_perm(b1.x, b1.y, 0x7632), __byte_perm(b1.z, b1.w, 0x7632));

    ((uint4*)(g_ph + rowc))[tid] = c0;
    ((uint4*)(g_ph + rows))[tid] = s0;
    ((uint4*)(g_pl + rowc))[tid] = e0;
    ((uint4*)(g_pl + rows))[tid] = f0;
}

// ===========================================================================
// Kernel 2: bf16 hi/lo-split Gram via mma.sync.m16n8k16 (unchanged from R6).
// ===========================================================================
extern __shared__ __align__(128) char gsm[];   // 2 * BUFBYTES = 80 KB

__global__ void __launch_bounds__(256, 2) gram_mma() {
    const int tid  = threadIdx.x;
    const int wid  = tid >> 5;
    const int lane = tid & 31;
    const int ks   = blockIdx.x;
    const int tile = blockIdx.y;
    const int b    = blockIdx.z;
    const int ms   = (tile >= 1) ? 1 : 0;
    const int ns   = (tile == 1) ? 1 : 0;
    const bool diag = (ms == ns);

    const uint32_t sb = smem_u32(gsm);
    const size_t k0 = (size_t)ks * (T_LEN / KSPLIT);

    const int sub  = tid & 3;
    const int vrw  = tid >> 2;
    const int npass = diag ? 4 : 8;

    int prow[8]; const __nv_bfloat16* psrc[8]; uint32_t pdst[8];
#pragma unroll
    for (int p = 0; p < 8; p++) {
        const int vr = vrw + p * 64;
        const int q  = vr >> 7;              // 0=Ahi 1=Alo 2=Bhi 3=Blo
        const int r  = vr & 127;
        psrc[p] = (q & 1) ? g_pl : g_ph;
        prow[p] = (b * 256 + ((q < 2) ? ms : ns) * 128 + r);
        pdst[p] = (uint32_t)(q * MATBYTES + r * (ROWSTRIDE * 2) + sub * 16);
    }

    auto load_chunk = [&](int c) {
        const uint32_t bufb = sb + (uint32_t)((c & 1) * BUFBYTES);
        const size_t kofs = k0 + (size_t)c * KC + sub * 8;
#pragma unroll
        for (int p = 0; p < 8; p++) {
            if (p >= npass) break;
            cp16(bufb + pdst[p], psrc[p] + (size_t)prow[p] * T_LEN + kofs);
        }
        CP_COMMIT();
    };

    const int mrow0 = (wid >> 2) * 64;
    const int ncol0 = (wid & 3) * 32;

    float acc[4][4][4];
#pragma unroll
    for (int mt = 0; mt < 4; mt++)
#pragma unroll
        for (int nt = 0; nt < 4; nt++)
#pragma unroll
            for (int e = 0; e < 4; e++) acc[mt][nt][e] = 0.0f;

    const uint32_t bOfsHi = diag ? 0u : (uint32_t)(2 * MATBYTES);
    const uint32_t bOfsLo = diag ? (uint32_t)MATBYTES : (uint32_t)(3 * MATBYTES);

    load_chunk(0);
    for (int c = 0; c < NC; c++) {
        if (c + 1 < NC) { load_chunk(c + 1); CP_WAIT1(); }
        else           { CP_WAIT0(); }
        __syncthreads();

        const uint32_t bufb = sb + (uint32_t)((c & 1) * BUFBYTES);
#pragma unroll
        for (int kstep = 0; kstep < KC / 16; kstep++) {
            uint32_t bh[4][2], bl[4][2];
            const int brow  = ncol0 + (lane & 7);
            const int bcolb = ((((lane >> 3) & 1) << 3) + kstep * 16) * 2;
#pragma unroll
            for (int nt = 0; nt < 4; nt++) {
                const uint32_t bo = (uint32_t)((brow + nt * 8) * (ROWSTRIDE * 2) + bcolb);
                ldsm2(bh[nt], bufb + bOfsHi + bo);
                ldsm2(bl[nt], bufb + bOfsLo + bo);
            }
            const int arow  = mrow0 + (lane & 15);
            const int acolb = (((lane >> 4) << 3) + kstep * 16) * 2;
#pragma unroll
            for (int mt = 0; mt < 4; mt++) {
                uint32_t ah[4], al[4];
                const uint32_t ao = (uint32_t)((arow + mt * 16) * (ROWSTRIDE * 2) + acolb);
                ldsm4(ah, bufb + ao);
                ldsm4(al, bufb + MATBYTES + ao);
#pragma unroll
                for (int nt = 0; nt < 4; nt++) {
                    mma_bf16(acc[mt][nt], ah, bh[nt]);
                    mma_bf16(acc[mt][nt], ah, bl[nt]);
                    mma_bf16(acc[mt][nt], al, bh[nt]);
                }
            }
        }
        __syncthreads();
    }

    float* __restrict__ G =
        g_gram + ((size_t)((ks * BATCH + b) * 3 + tile)) * (CH * CH);
    const int r0 = lane >> 2;
    const int c0 = (lane & 3) * 2;
#pragma unroll
    for (int mt = 0; mt < 4; mt++) {
        const int row = mrow0 + mt * 16 + r0;
#pragma unroll
        for (int nt = 0; nt < 4; nt++) {
            const int col = ncol0 + nt * 8 + c0;
            *(float2*)(G + row * CH + col) =
                make_float2(acc[mt][nt][0], acc[mt][nt][1]);
            *(float2*)(G + (row + 8) * CH + col) =
                make_float2(acc[mt][nt][2], acc[mt][nt][3]);
        }
    }
}

// ===========================================================================
// Kernel 3: combine K-splits; Re = CC+SS, Im = SC[i,j]-SC[j,i]; PLV=|.|/T.
// ===========================================================================
__global__ void finalize_kernel(float* __restrict__ out) {
    const int idx = blockIdx.x * blockDim.x + threadIdx.x;
    if (idx >= BATCH * CH * CH) return;
    const int b  = idx >> 14;
    const int ij = idx & 16383;
    const int i  = ij >> 7;
    const int j  = ij & 127;
    float re = 0.0f, im = 0.0f;
#pragma unroll
    for (int ks = 0; ks < KSPLIT; ks++) {
        const float* __restrict__ base =
            g_gram + ((size_t)((ks * BATCH + b) * 3)) * (CH * CH);
        re += base[ij] + base[CH * CH + ij];                       // CC + SS
        im += base[2 * CH * CH + i * CH + j]
            - base[2 * CH * CH + j * CH + i];                      // SC - SC^T
    }
    out[idx] = sqrtf(re * re + im * im) * (1.0f / (float)T_LEN);
}

// ===========================================================================
extern "C" void kernel_launch(void* const* d_in, const int* in_sizes, int n_in,
                              void* d_out, int out_size) {
    const float* x = (const float*)d_in[0];
    float* out = (float*)d_out;

    const int fft_smem = (T_LEN + HALF) * (int)sizeof(float2);  // 96 KB
    cudaFuncSetAttribute(fft_kernel, cudaFuncAttributeMaxDynamicSharedMemorySize,
                         fft_smem);
    cudaFuncSetAttribute(gram_mma, cudaFuncAttributeMaxDynamicSharedMemorySize,
                         2 * BUFBYTES);

    fft_kernel<<<NSIG, 1024, fft_smem>>>(x);
    gram_mma<<<dim3(KSPLIT, 3, BATCH), 256, 2 * BUFBYTES>>>();
    finalize_kernel<<<(BATCH * CH * CH + 255) / 256, 256>>>(out);
}

// round 9
// speedup vs baseline: 1.2852x; 1.1282x over previous
#include <cuda_runtime.h>
#include <cuda_bf16.h>
#include <math.h>
#include <stdint.h>

#define T_LEN 8192
#define HALF  4096
#define CH    128
#define BATCH 16
#define NSIG  (BATCH * CH)
#define KSPLIT 16
#define KC    32                          // K per chunk
#define NC    (T_LEN / KSPLIT / KC)       // 16 chunks per CTA
#define ROWSTRIDE 40                      // bf16 elems per smem row (32 + 8 pad)
#define MATBYTES (128 * ROWSTRIDE * 2)    // 10240
#define BUFBYTES (4 * MATBYTES)           // 40960

// Scratch (alloc-free rule: __device__ globals)
__device__ __nv_bfloat16 g_ph[(size_t)BATCH * 256 * T_LEN];   // hi parts: 64 MB
__device__ __nv_bfloat16 g_pl[(size_t)BATCH * 256 * T_LEN];   // lo parts: 64 MB
__device__ float g_gram[(size_t)KSPLIT * BATCH * 3 * CH * CH];// Gram tiles: 48 MB

// ===========================================================================
// PTX helpers (sm_103 family-portable: ldmatrix / mma.sync / cp.async)
// ===========================================================================
__device__ __forceinline__ uint32_t smem_u32(const void* p) {
    uint32_t a;
    asm("{ .reg .u64 t; cvta.to.shared.u64 t, %1; cvt.u32.u64 %0, t; }"
        : "=r"(a) : "l"(p));
    return a;
}
__device__ __forceinline__ void ldsm4(uint32_t* d, uint32_t addr) {
    asm volatile("ldmatrix.sync.aligned.m8n8.x4.shared.b16 {%0,%1,%2,%3}, [%4];"
                 : "=r"(d[0]), "=r"(d[1]), "=r"(d[2]), "=r"(d[3]) : "r"(addr));
}
__device__ __forceinline__ void ldsm2(uint32_t* d, uint32_t addr) {
    asm volatile("ldmatrix.sync.aligned.m8n8.x2.shared.b16 {%0,%1}, [%2];"
                 : "=r"(d[0]), "=r"(d[1]) : "r"(addr));
}
__device__ __forceinline__ void mma_bf16(float* d, const uint32_t* a, const uint32_t* b) {
    asm volatile(
        "mma.sync.aligned.m16n8k16.row.col.f32.bf16.bf16.f32 "
        "{%0,%1,%2,%3}, {%4,%5,%6,%7}, {%8,%9}, {%0,%1,%2,%3};"
        : "+f"(d[0]), "+f"(d[1]), "+f"(d[2]), "+f"(d[3])
        : "r"(a[0]), "r"(a[1]), "r"(a[2]), "r"(a[3]), "r"(b[0]), "r"(b[1]));
}
__device__ __forceinline__ void cp16(uint32_t smem, const void* g) {
    asm volatile("cp.async.cg.shared.global [%0], [%1], 16;"
                 :: "r"(smem), "l"(g) : "memory");
}
#define CP_COMMIT() asm volatile("cp.async.commit_group;" ::: "memory")
#define CP_WAIT1()  asm volatile("cp.async.wait_group 1;" ::: "memory")
#define CP_WAIT0()  asm volatile("cp.async.wait_group 0;" ::: "memory")

// ===========================================================================
// Kernel 1: register-resident FFT (512 thr x 16 elems, 6 exchanges = R6 shape)
// with template-specialized per-stage twiddle hoisting (15 loads per 4-stage
// group instead of 32). Packed bf16x2 epilogue (validated in R7/R8).
// ===========================================================================
__device__ __forceinline__ int swz(int i) { return i ^ ((i >> 5) & 31); }

// One radix-2 stage at local bit LB. All sizes/indices compile-time.
template<int P, int LB, int FWD>
__device__ __forceinline__ void stage_one(float2 v[16], int base,
                                          const float2* __restrict__ tw) {
    const int s  = P + LB;
    const int bm = base & ((1 << s) - 1);
    // Hoist distinct twiddles for LB<3 (reuse factor 8/4/2); LB==3 has none.
    float2 wc[(LB < 3) ? (1 << LB) : 1];
    if (LB < 3) {
#pragma unroll
        for (int q = 0; q < (1 << LB); q++)
            wc[q] = tw[(bm + (q << P)) << (12 - s)];
    }
#pragma unroll
    for (int rr = 0; rr < 16; rr++) {
        if ((rr >> LB) & 1) continue;
        const int r1 = rr | (1 << LB);
        float2 w;
        if (LB < 3) w = wc[rr & ((1 << LB) - 1)];
        else        w = tw[(bm + ((rr & 7) << P)) << (12 - s)];
        float2 a = v[rr], b = v[r1];
        if (FWD) {
            v[rr] = make_float2(a.x + b.x, a.y + b.y);
            float2 d = make_float2(a.x - b.x, a.y - b.y);
            v[r1] = make_float2(d.x * w.x - d.y * w.y, d.x * w.y + d.y * w.x);
        } else {
            float2 tt = make_float2(b.x * w.x + b.y * w.y, b.y * w.x - b.x * w.y);
            v[rr] = make_float2(a.x + tt.x, a.y + tt.y);
            v[r1] = make_float2(a.x - tt.x, a.y - tt.y);
        }
    }
}

// Stage groups with explicit order (FWD: LB high->low, INV: low->high).
template<int P, int FWD, int LBLO, int LBHI>
__device__ __forceinline__ void stages(float2 v[16], int base,
                                       const float2* __restrict__ tw) {
    if (FWD) {
        if (LBHI >= 3 && 3 >= LBLO) stage_one<P, 3, 1>(v, base, tw);
        if (LBHI >= 2 && 2 >= LBLO) stage_one<P, 2, 1>(v, base, tw);
        if (LBHI >= 1 && 1 >= LBLO) stage_one<P, 1, 1>(v, base, tw);
        if (LBHI >= 0 && 0 >= LBLO) stage_one<P, 0, 1>(v, base, tw);
    } else {
        if (LBLO <= 0 && 0 <= LBHI) stage_one<P, 0, 0>(v, base, tw);
        if (LBLO <= 1 && 1 <= LBHI) stage_one<P, 1, 0>(v, base, tw);
        if (LBLO <= 2 && 2 <= LBHI) stage_one<P, 2, 0>(v, base, tw);
        if (LBLO <= 3 && 3 <= LBHI) stage_one<P, 3, 0>(v, base, tw);
    }
}

extern __shared__ float2 smm[];   // fft: [0..8191]=exchange, [8192..12287]=twiddles

__global__ void __launch_bounds__(512) fft_kernel(const float* __restrict__ x) {
    float2* sm = smm;
    float2* tw = smm + T_LEN;
    const int tid = threadIdx.x;
    const long long gbase = (long long)blockIdx.x * T_LEN;

    for (int t = tid; t < HALF; t += 512) {
        float s, c;
        sincosf(-6.283185307179586e0f * (float)t / (float)T_LEN, &s, &c);
        tw[t] = make_float2(c, s);
    }

    const int baseA = tid;                                  // P=9
    const int baseB = ((tid >> 5) << 9) + (tid & 31);       // P=5
    const int baseC = ((tid >> 1) << 5) + (tid & 1);        // P=1
    const int baseD = tid << 4;                             // P=0
    const int baseE = ((tid >> 4) << 8) + (tid & 15);       // P=4
    const int baseF = ((tid >> 8) << 12) + (tid & 255);     // P=8

    float2 v[16];
#pragma unroll
    for (int r = 0; r < 16; r++)
        v[r] = make_float2(x[gbase + tid + r * 512], 0.0f);
    __syncthreads();

    // ---- forward DIF ----
    stages<9, 1, 0, 3>(v, baseA, tw);                       // s = 12..9
#pragma unroll
    for (int r = 0; r < 16; r++) sm[swz(baseA + (r << 9))] = v[r];
    __syncthreads();
#pragma unroll
    for (int r = 0; r < 16; r++) v[r] = sm[swz(baseB + (r << 5))];
    __syncthreads();

    stages<5, 1, 0, 3>(v, baseB, tw);                       // s = 8..5
#pragma unroll
    for (int r = 0; r < 16; r++) sm[swz(baseB + (r << 5))] = v[r];
    __syncthreads();
#pragma unroll
    for (int r = 0; r < 16; r++) v[r] = sm[swz(baseC + (r << 1))];
    __syncthreads();

    stages<1, 1, 0, 3>(v, baseC, tw);                       // s = 4..1
#pragma unroll
    for (int r = 0; r < 16; r++) sm[swz(baseC + (r << 1))] = v[r];
    __syncthreads();
#pragma unroll
    for (int r = 0; r < 16; r++) v[r] = sm[swz(baseD + r)];
    __syncthreads();

    // Fused: fwd stage 0 (w=1) + mask(odd bit-rev pos) + inv stage 0.
#pragma unroll
    for (int r = 0; r < 16; r += 2) {
        float2 s0 = make_float2(v[r].x + v[r + 1].x, v[r].y + v[r + 1].y);
        v[r] = s0; v[r + 1] = s0;
    }

    // ---- inverse DIT ----
    stages<0, 0, 1, 3>(v, baseD, tw);                       // s = 1..3
#pragma unroll
    for (int r = 0; r < 16; r++) sm[swz(baseD + r)] = v[r];
    __syncthreads();
#pragma unroll
    for (int r = 0; r < 16; r++) v[r] = sm[swz(baseE + (r << 4))];
    __syncthreads();

    stages<4, 0, 0, 3>(v, baseE, tw);                       // s = 4..7
#pragma unroll
    for (int r = 0; r < 16; r++) sm[swz(baseE + (r << 4))] = v[r];
    __syncthreads();
#pragma unroll
    for (int r = 0; r < 16; r++) v[r] = sm[swz(baseF + (r << 8))];
    __syncthreads();

    stages<8, 0, 0, 3>(v, baseF, tw);                       // s = 8..11
#pragma unroll
    for (int r = 0; r < 16; r++) sm[swz(baseF + (r << 8))] = v[r];
    __syncthreads();
#pragma unroll
    for (int r = 0; r < 16; r++) v[r] = sm[swz(baseA + (r << 9))];
    __syncthreads();

    stages<9, 0, 3, 3>(v, baseA, tw);                       // s = 12

    // ---- epilogue: normalize, bf16 hi/lo split, packed smem staging ----
    uint32_t* sbA = (uint32_t*)sm;          // (chh | shh<<16) per t
    uint32_t* sbB = sbA + T_LEN;            // (cll | sll<<16)
#pragma unroll
    for (int r = 0; r < 16; r++) {
        const int t = tid + r * 512;
        float2 u = v[r];
        float m2 = u.x * u.x + u.y * u.y;
        float cx, sx;
        if (m2 > 0.0f) {
            float inv = rsqrtf(m2);
            cx = u.x * inv; sx = u.y * inv;
        } else {
            cx = 1.0f; sx = 0.0f;
        }
        __nv_bfloat16 chh = __float2bfloat16(cx);
        __nv_bfloat16 cll = __float2bfloat16(cx - __bfloat162float(chh));
        __nv_bfloat16 shh = __float2bfloat16(sx);
        __nv_bfloat16 sll = __float2bfloat16(sx - __bfloat162float(shh));
        sbA[t] = (uint32_t)__bfloat16_as_ushort(chh)
               | ((uint32_t)__bfloat16_as_ushort(shh) << 16);
        sbB[t] = (uint32_t)__bfloat16_as_ushort(cll)
               | ((uint32_t)__bfloat16_as_ushort(sll) << 16);
    }
    __syncthreads();

    const int bb = blockIdx.x >> 7;
    const int cc = blockIdx.x & 127;
    const size_t rowc = ((size_t)bb * 256 + cc) * T_LEN;
    const size_t rows = rowc + (size_t)128 * T_LEN;

    // Each thread covers t in [16*tid, 16*tid+16): unzip pairs -> STG.128
    const uint4* A4 = (const uint4*)sbA;
    const uint4* B4 = (const uint4*)sbB;
    uint4 a0 = A4[4 * tid], a1 = A4[4 * tid + 1];
    uint4 a2 = A4[4 * tid + 2], a3 = A4[4 * tid + 3];
    uint4 b0 = B4[4 * tid], b1 = B4[4 * tid + 1];
    uint4 b2 = B4[4 * tid + 2], b3 = B4[4 * tid + 3];

    uint4 c0 = make_uint4(__byte_perm(a0.x, a0.y, 0x5410), __byte_perm(a0.z, a0.w, 0x5410),
                          __byte_perm(a1.x, a1.y, 0x5410), __byte_perm(a1.z, a1.w, 0x5410));
    uint4 c1 = make_uint4(__byte_perm(a2.x, a2.y, 0x5410), __byte_perm(a2.z, a2.w, 0x5410),
                          __byte_perm(a3.x, a3.y, 0x5410), __byte_perm(a3.z, a3.w, 0x5410));
    uint4 s0 = make_uint4(__byte_perm(a0.x, a0.y, 0x7632), __byte_perm(a0.z, a0.w, 0x7632),
                          __byte_perm(a1.x, a1.y, 0x7632), __byte_perm(a1.z, a1.w, 0x7632));
    uint4 s1 = make_uint4(__byte_perm(a2.x, a2.y, 0x7632), __byte_perm(a2.z, a2.w, 0x7632),
                          __byte_perm(a3.x, a3.y, 0x7632), __byte_perm(a3.z, a3.w, 0x7632));
    uint4 e0 = make_uint4(__byte_perm(b0.x, b0.y, 0x5410), __byte_perm(b0.z, b0.w, 0x5410),
                          __byte_perm(b1.x, b1.y, 0x5410), __byte_perm(b1.z, b1.w, 0x5410));
    uint4 e1 = make_uint4(__byte_perm(b2.x, b2.y, 0x5410), __byte_perm(b2.z, b2.w, 0x5410),
                          __byte_perm(b3.x, b3.y, 0x5410), __byte_perm(b3.z, b3.w, 0x5410));
    uint4 f0 = make_uint4(__byte_perm(b0.x, b0.y, 0x7632), __byte_perm(b0.z, b0.w, 0x7632),
                          __byte_perm(b1.x, b1.y, 0x7632), __byte_perm(b1.z, b1.w, 0x7632));
    uint4 f1 = make_uint4(__byte_perm(b2.x, b2.y, 0x7632), __byte_perm(b2.z, b2.w, 0x7632),
                          __byte_perm(b3.x, b3.y, 0x7632), __byte_perm(b3.z, b3.w, 0x7632));

    ((uint4*)(g_ph + rowc))[2 * tid]     = c0;
    ((uint4*)(g_ph + rowc))[2 * tid + 1] = c1;
    ((uint4*)(g_ph + rows))[2 * tid]     = s0;
    ((uint4*)(g_ph + rows))[2 * tid + 1] = s1;
    ((uint4*)(g_pl + rowc))[2 * tid]     = e0;
    ((uint4*)(g_pl + rowc))[2 * tid + 1] = e1;
    ((uint4*)(g_pl + rows))[2 * tid]     = f0;
    ((uint4*)(g_pl + rows))[2 * tid + 1] = f1;
}

// ===========================================================================
// Kernel 2: bf16 hi/lo-split Gram via mma.sync.m16n8k16 (unchanged from R6).
// ===========================================================================
extern __shared__ __align__(128) char gsm[];   // 2 * BUFBYTES = 80 KB

__global__ void __launch_bounds__(256, 2) gram_mma() {
    const int tid  = threadIdx.x;
    const int wid  = tid >> 5;
    const int lane = tid & 31;
    const int ks   = blockIdx.x;
    const int tile = blockIdx.y;
    const int b    = blockIdx.z;
    const int ms   = (tile >= 1) ? 1 : 0;
    const int ns   = (tile == 1) ? 1 : 0;
    const bool diag = (ms == ns);

    const uint32_t sb = smem_u32(gsm);
    const size_t k0 = (size_t)ks * (T_LEN / KSPLIT);

    const int sub  = tid & 3;
    const int vrw  = tid >> 2;
    const int npass = diag ? 4 : 8;

    int prow[8]; const __nv_bfloat16* psrc[8]; uint32_t pdst[8];
#pragma unroll
    for (int p = 0; p < 8; p++) {
        const int vr = vrw + p * 64;
        const int q  = vr >> 7;              // 0=Ahi 1=Alo 2=Bhi 3=Blo
        const int r  = vr & 127;
        psrc[p] = (q & 1) ? g_pl : g_ph;
        prow[p] = (b * 256 + ((q < 2) ? ms : ns) * 128 + r);
        pdst[p] = (uint32_t)(q * MATBYTES + r * (ROWSTRIDE * 2) + sub * 16);
    }

    auto load_chunk = [&](int c) {
        const uint32_t bufb = sb + (uint32_t)((c & 1) * BUFBYTES);
        const size_t kofs = k0 + (size_t)c * KC + sub * 8;
#pragma unroll
        for (int p = 0; p < 8; p++) {
            if (p >= npass) break;
            cp16(bufb + pdst[p], psrc[p] + (size_t)prow[p] * T_LEN + kofs);
        }
        CP_COMMIT();
    };

    const int mrow0 = (wid >> 2) * 64;
    const int ncol0 = (wid & 3) * 32;

    float acc[4][4][4];
#pragma unroll
    for (int mt = 0; mt < 4; mt++)
#pragma unroll
        for (int nt = 0; nt < 4; nt++)
#pragma unroll
            for (int e = 0; e < 4; e++) acc[mt][nt][e] = 0.0f;

    const uint32_t bOfsHi = diag ? 0u : (uint32_t)(2 * MATBYTES);
    const uint32_t bOfsLo = diag ? (uint32_t)MATBYTES : (uint32_t)(3 * MATBYTES);

    load_chunk(0);
    for (int c = 0; c < NC; c++) {
        if (c + 1 < NC) { load_chunk(c + 1); CP_WAIT1(); }
        else           { CP_WAIT0(); }
        __syncthreads();

        const uint32_t bufb = sb + (uint32_t)((c & 1) * BUFBYTES);
#pragma unroll
        for (int kstep = 0; kstep < KC / 16; kstep++) {
            uint32_t bh[4][2], bl[4][2];
            const int brow  = ncol0 + (lane & 7);
            const int bcolb = ((((lane >> 3) & 1) << 3) + kstep * 16) * 2;
#pragma unroll
            for (int nt = 0; nt < 4; nt++) {
                const uint32_t bo = (uint32_t)((brow + nt * 8) * (ROWSTRIDE * 2) + bcolb);
                ldsm2(bh[nt], bufb + bOfsHi + bo);
                ldsm2(bl[nt], bufb + bOfsLo + bo);
            }
            const int arow  = mrow0 + (lane & 15);
            const int acolb = (((lane >> 4) << 3) + kstep * 16) * 2;
#pragma unroll
            for (int mt = 0; mt < 4; mt++) {
                uint32_t ah[4], al[4];
                const uint32_t ao = (uint32_t)((arow + mt * 16) * (ROWSTRIDE * 2) + acolb);
                ldsm4(ah, bufb + ao);
                ldsm4(al, bufb + MATBYTES + ao);
#pragma unroll
                for (int nt = 0; nt < 4; nt++) {
                    mma_bf16(acc[mt][nt], ah, bh[nt]);
                    mma_bf16(acc[mt][nt], ah, bl[nt]);
                    mma_bf16(acc[mt][nt], al, bh[nt]);
                }
            }
        }
        __syncthreads();
    }

    float* __restrict__ G =
        g_gram + ((size_t)((ks * BATCH + b) * 3 + tile)) * (CH * CH);
    const int r0 = lane >> 2;
    const int c0 = (lane & 3) * 2;
#pragma unroll
    for (int mt = 0; mt < 4; mt++) {
        const int row = mrow0 + mt * 16 + r0;
#pragma unroll
        for (int nt = 0; nt < 4; nt++) {
            const int col = ncol0 + nt * 8 + c0;
            *(float2*)(G + row * CH + col) =
                make_float2(acc[mt][nt][0], acc[mt][nt][1]);
            *(float2*)(G + (row + 8) * CH + col) =
                make_float2(acc[mt][nt][2], acc[mt][nt][3]);
        }
    }
}

// ===========================================================================
// Kernel 3: combine K-splits; Re = CC+SS, Im = SC[i,j]-SC[j,i]; PLV=|.|/T.
// ===========================================================================
__global__ void finalize_kernel(float* __restrict__ out) {
    const int idx = blockIdx.x * blockDim.x + threadIdx.x;
    if (idx >= BATCH * CH * CH) return;
    const int b  = idx >> 14;
    const int ij = idx & 16383;
    const int i  = ij >> 7;
    const int j  = ij & 127;
    float re = 0.0f, im = 0.0f;
#pragma unroll
    for (int ks = 0; ks < KSPLIT; ks++) {
        const float* __restrict__ base =
            g_gram + ((size_t)((ks * BATCH + b) * 3)) * (CH * CH);
        re += base[ij] + base[CH * CH + ij];                       // CC + SS
        im += base[2 * CH * CH + i * CH + j]
            - base[2 * CH * CH + j * CH + i];                      // SC - SC^T
    }
    out[idx] = sqrtf(re * re + im * im) * (1.0f / (float)T_LEN);
}

// ===========================================================================
extern "C" void kernel_launch(void* const* d_in, const int* in_sizes, int n_in,
                              void* d_out, int out_size) {
    const float* x = (const float*)d_in[0];
    float* out = (float*)d_out;

    const int fft_smem = (T_LEN + HALF) * (int)sizeof(float2);  // 96 KB
    cudaFuncSetAttribute(fft_kernel, cudaFuncAttributeMaxDynamicSharedMemorySize,
                         fft_smem);
    cudaFuncSetAttribute(gram_mma, cudaFuncAttributeMaxDynamicSharedMemorySize,
                         2 * BUFBYTES);

    fft_kernel<<<NSIG, 512, fft_smem>>>(x);
    gram_mma<<<dim3(KSPLIT, 3, BATCH), 256, 2 * BUFBYTES>>>();
    finalize_kernel<<<(BATCH * CH * CH + 255) / 256, 256>>>(out);
}